// round 9
// baseline (speedup 1.0000x reference)
#include <cuda_runtime.h>
#include <math.h>
#include <stdint.h>

#define B_  16
#define D_  96
#define T_  512
#define H_  1024
#define BD_ (B_*D_)

// ---- scratch ----
__device__ float g_A[B_*D_*D_];    // softmax corr, tf32-rounded
__device__ float g_x1[BD_*T_];     // attn+res (for BN stats)
__device__ float g_x2r[BD_*T_];    // BN(x1) tf32-rounded (GEMM1 A + GEMM2 residual)
__device__ float g_h[BD_*H_];      // GELU output, tf32-rounded
__device__ float g_y[BD_*T_];
__device__ float g_w1t[H_*T_];     // W1^T [H][T], tf32-rounded
__device__ float g_w2t[T_*H_];     // W2^T [T][H], tf32-rounded

extern __shared__ char dyn_smem[];

__device__ __forceinline__ float warp_sum(float v){
    #pragma unroll
    for(int o=16;o>0;o>>=1) v += __shfl_xor_sync(0xffffffffu, v, o);
    return v;
}
__device__ __forceinline__ float warp_max(float v){
    #pragma unroll
    for(int o=16;o>0;o>>=1) v = fmaxf(v, __shfl_xor_sync(0xffffffffu, v, o));
    return v;
}
__device__ __forceinline__ float to_tf32f(float x){
    uint32_t u; asm("cvt.rna.tf32.f32 %0, %1;" : "=r"(u) : "f"(x));
    return __uint_as_float(u);
}
__device__ __forceinline__ uint32_t smem_u32(const void* p){
    uint32_t a;
    asm("{ .reg .u64 t; cvta.to.shared.u64 t, %1; cvt.u32.u64 %0, t; }" : "=r"(a) : "l"(p));
    return a;
}
__device__ __forceinline__ void mma_tf32(float4& d, const uint32_t a[4], uint32_t b0, uint32_t b1){
    asm volatile("mma.sync.aligned.m16n8k8.row.col.f32.tf32.tf32.f32 "
        "{%0,%1,%2,%3}, {%4,%5,%6,%7}, {%8,%9}, {%0,%1,%2,%3};"
        : "+f"(d.x), "+f"(d.y), "+f"(d.z), "+f"(d.w)
        : "r"(a[0]), "r"(a[1]), "r"(a[2]), "r"(a[3]), "r"(b0), "r"(b1));
}
__device__ __forceinline__ void ldsm_x4(uint32_t* r, uint32_t addr){
    asm volatile("ldmatrix.sync.aligned.m8n8.x4.shared.b16 {%0,%1,%2,%3}, [%4];"
        : "=r"(r[0]), "=r"(r[1]), "=r"(r[2]), "=r"(r[3]) : "r"(addr));
}
__device__ __forceinline__ void cp16(uint32_t dst, const void* src){
    asm volatile("cp.async.ca.shared.global [%0], [%1], 16;" :: "r"(dst), "l"(src));
}
#define CP_COMMIT() asm volatile("cp.async.commit_group;" ::: "memory")
#define CP_WAIT1()  asm volatile("cp.async.wait_group 1;" ::: "memory")
#define CP_WAIT0()  asm volatile("cp.async.wait_group 0;" ::: "memory")

// K0: merged weight transposes + corr softmax. grid 1040 x 256 thr.
// blocks [0,512): W1 tiles; [512,1024): W2 tiles; [1024,1040): per-batch corr.
__global__ void k_pre(const float* __restrict__ W1, float* __restrict__ W1t,
                      const float* __restrict__ W2, float* __restrict__ W2t,
                      const float* __restrict__ res){
    __shared__ float tile[32][33];
    __shared__ float s[D_];
    int bid = blockIdx.x;
    if (bid < 1024){
        const float* W; float* Wt; int R, C, bx, by;
        if (bid < 512){ W = W1; Wt = W1t; R = T_; C = H_;
            bx = (bid & 31)*32; by = (bid >> 5)*32; }
        else { int idx = bid - 512; W = W2; Wt = W2t; R = H_; C = T_;
            bx = (idx & 15)*32; by = (idx >> 4)*32; }
        int tx = threadIdx.x & 31, ty = threadIdx.x >> 5;
        #pragma unroll
        for (int r = 0; r < 4; r++)
            tile[ty + r*8][tx] = to_tf32f(W[(size_t)(by + ty + r*8)*C + bx + tx]);
        __syncthreads();
        #pragma unroll
        for (int r = 0; r < 4; r++)
            Wt[(size_t)(bx + ty + r*8)*R + by + tx] = tile[tx][ty + r*8];
        return;
    }
    // ---- corr: rank-1 softmax for batch b ----
    int b = bid - 1024;
    int w = threadIdx.x >> 5, lane = threadIdx.x & 31;
    for (int r = w; r < D_; r += 8){
        const float4* p = (const float4*)(res + (b*D_ + r)*T_);
        float v = 0.f;
        #pragma unroll
        for (int k = 0; k < 4; k++){
            float4 q = p[lane + k*32];
            v += (q.x + q.y) + (q.z + q.w);
        }
        v = warp_sum(v);
        if (lane == 0) s[r] = v;
    }
    __syncthreads();
    const float SCALE = 1.0f/11585.237502960395f;   // 1/512^1.5
    for (int r = w; r < D_; r += 8){
        float si = s[r];
        float z0 = si * s[lane     ] * SCALE;
        float z1 = si * s[lane + 32] * SCALE;
        float z2 = si * s[lane + 64] * SCALE;
        float m = warp_max(fmaxf(z0, fmaxf(z1, z2)));
        float e0 = expf(z0 - m), e1 = expf(z1 - m), e2 = expf(z2 - m);
        float inv = 1.f / warp_sum(e0 + e1 + e2);
        float* o = g_A + (b*D_ + r)*D_;
        o[lane]      = to_tf32f(e0 * inv);
        o[lane + 32] = to_tf32f(e1 * inv);
        o[lane + 64] = to_tf32f(e2 * inv);
    }
}

// K2: x1 = (I+A) @ X via tf32 mma. grid (T/64, B), 256 thr.
// sA [128 m][100 f] (rows 96-127 garbage, discarded), sB [64 t][100 f] = X^T rounded.
#define AT_SB_OFF (128*100)
#define ATTN_SMEM ((128*100 + 64*100)*4)   // 76800 B
__global__ void __launch_bounds__(256) k_attn(const float* __restrict__ res){
    float* sm = (float*)dyn_smem;
    float* sA = sm;
    float* sB = sm + AT_SB_OFF;
    uint32_t sbase = smem_u32(sm);
    int b  = blockIdx.y;
    int t0 = blockIdx.x * 64;
    int tid = threadIdx.x, lane = tid & 31, w = tid >> 5;

    // stage A [96x96] (already tf32-rounded)
    for (int i = tid; i < D_*D_/4; i += 256){
        int d = (i*4)/D_, e = (i*4)%D_;
        *(float4*)&sA[d*100 + e] = *(const float4*)&g_A[(b*D_+d)*D_ + e];
    }
    // stage X^T: sB[n][e] = tf32(res[b,e,t0+n])
    for (int i = tid; i < D_*64; i += 256){
        int e = i >> 6, n = i & 63;
        sB[n*100 + e] = to_tf32f(res[(b*D_+e)*T_ + t0 + n]);
    }
    __syncthreads();

    int wm = (w & 3) * 32, wn = (w >> 2) * 32;
    uint32_t aF0, aF1, bF0, bF1;
    {
        int rlo = lane & 7, rmid = (lane >> 3) & 1, khi = lane >> 4;
        aF0 = sbase + (uint32_t)((wm + rlo + 8*rmid)*400 + 16*khi);
        aF1 = aF0 + 16*400;
        bF0 = sbase + (uint32_t)(AT_SB_OFF*4 + (wn      + khi*8 + rlo)*400 + 16*rmid);
        bF1 = sbase + (uint32_t)(AT_SB_OFF*4 + (wn + 16 + khi*8 + rlo)*400 + 16*rmid);
    }
    float4 acc[2][4];
    #pragma unroll
    for (int i = 0; i < 2; i++)
        #pragma unroll
        for (int j = 0; j < 4; j++) acc[i][j] = make_float4(0.f,0.f,0.f,0.f);

    #pragma unroll
    for (int ks = 0; ks < 12; ks++){
        uint32_t a0[4], a1[4], b0[4], b1[4];
        ldsm_x4(a0, aF0 + ks*32);
        ldsm_x4(a1, aF1 + ks*32);
        ldsm_x4(b0, bF0 + ks*32);
        ldsm_x4(b1, bF1 + ks*32);
        mma_tf32(acc[0][0], a0, b0[0], b0[1]);
        mma_tf32(acc[0][1], a0, b0[2], b0[3]);
        mma_tf32(acc[0][2], a0, b1[0], b1[1]);
        mma_tf32(acc[0][3], a0, b1[2], b1[3]);
        mma_tf32(acc[1][0], a1, b0[0], b0[1]);
        mma_tf32(acc[1][1], a1, b0[2], b0[3]);
        mma_tf32(acc[1][2], a1, b1[0], b1[1]);
        mma_tf32(acc[1][3], a1, b1[2], b1[3]);
    }

    if (wm < 96){
        int tr = lane >> 2, tc = lane & 3;
        #pragma unroll
        for (int i = 0; i < 2; i++){
            int r0 = wm + i*16 + tr;     // d index
            int r1 = r0 + 8;
            #pragma unroll
            for (int j = 0; j < 4; j++){
                int cl = wn + j*8 + tc*2;  // local t
                float4 v = acc[i][j];
                v.x += sB[cl*100 + r0];  v.y += sB[(cl+1)*100 + r0];
                v.z += sB[cl*100 + r1];  v.w += sB[(cl+1)*100 + r1];
                *(float2*)&g_x1[(b*D_+r0)*T_ + t0 + cl] = make_float2(v.x, v.y);
                *(float2*)&g_x1[(b*D_+r1)*T_ + t0 + cl] = make_float2(v.z, v.w);
            }
        }
    }
}

// K3: fused BN stats + apply, single read (data held in registers). grid=D_, 512 thr.
__global__ void k_bn(const float* __restrict__ gamma, const float* __restrict__ beta){
    int d = blockIdx.x;
    int tid = threadIdx.x;
    float4 v[4];
    float s = 0.f, ss = 0.f;
    #pragma unroll
    for (int r = 0; r < 4; r++){
        int i = tid + r*512;
        int b = i >> 7, t4 = i & 127;
        v[r] = *(const float4*)&g_x1[(b*D_+d)*T_ + t4*4];
        s  += (v[r].x + v[r].y) + (v[r].z + v[r].w);
        ss += (v[r].x*v[r].x + v[r].y*v[r].y) + (v[r].z*v[r].z + v[r].w*v[r].w);
    }
    s = warp_sum(s); ss = warp_sum(ss);
    __shared__ float r1[16], r2[16];
    __shared__ float bsc, bof;
    int w = tid >> 5;
    if ((tid & 31) == 0){ r1[w] = s; r2[w] = ss; }
    __syncthreads();
    if (tid == 0){
        float S = 0.f, SS = 0.f;
        #pragma unroll
        for (int k = 0; k < 16; k++){ S += r1[k]; SS += r2[k]; }
        const float invN = 1.f/(float)(B_*T_);
        float mean = S * invN;
        float var  = SS * invN - mean*mean;
        float rs = rsqrtf(var + 1e-5f);
        float sc = rs * gamma[d];
        bsc = sc; bof = beta[d] - mean * sc;
    }
    __syncthreads();
    float sc = bsc, of = bof;
    #pragma unroll
    for (int r = 0; r < 4; r++){
        int i = tid + r*512;
        int b = i >> 7, t4 = i & 127;
        float4 q = v[r];
        q.x = to_tf32f(fmaf(q.x, sc, of));
        q.y = to_tf32f(fmaf(q.y, sc, of));
        q.z = to_tf32f(fmaf(q.z, sc, of));
        q.w = to_tf32f(fmaf(q.w, sc, of));
        *(float4*)&g_x2r[(b*D_+d)*T_ + t4*4] = q;
    }
}

// ======================= tf32 mma.sync GEMM (ldmatrix + cp.async) =======================
#define ASTG 18432   // 128*36*4

template<int NW, bool GELU, bool ROUND, bool RESID>
__global__ void __launch_bounds__(256, 1) k_mma(
    const float* __restrict__ A, const float* __restrict__ Bt,
    const float* __restrict__ bias, const float* __restrict__ Res,
    float* __restrict__ C, int M, int N, int K)
{
    constexpr int BNT  = NW*32;
    constexpr int BSTG = BNT*144;
    constexpr int STG  = ASTG + BSTG;
    constexpr int NB4  = BNT/32;

    uint32_t sbase = smem_u32(dyn_smem);
    int tid = threadIdx.x, lane = tid & 31, w = tid >> 5;
    int wm = (w & 3) * 32, wn = (w >> 2) * (NW*16);
    int bn = blockIdx.x * BNT, bm = blockIdx.y * 128;

    uint32_t aSm[4]; const float* aG[4];
    #pragma unroll
    for (int r = 0; r < 4; r++){
        int idx = tid + r*256, m = idx >> 3, kc = idx & 7;
        aSm[r] = (uint32_t)(m*144 + kc*16);
        aG[r]  = A + (size_t)(bm + m)*K + kc*4;
    }
    uint32_t bSm[NB4]; const float* bG[NB4];
    #pragma unroll
    for (int r = 0; r < NB4; r++){
        int idx = tid + r*256, n = idx >> 3, kc = idx & 7;
        bSm[r] = (uint32_t)(ASTG + n*144 + kc*16);
        bG[r]  = Bt + (size_t)(bn + n)*K + kc*4;
    }

    uint32_t aF[2], bF[NW];
    {
        int rlo = lane & 7, rmid = (lane >> 3) & 1, khi = lane >> 4;
        aF[0] = (uint32_t)((wm + rlo + 8*rmid)*144 + 16*khi);
        aF[1] = aF[0] + 16*144;
        #pragma unroll
        for (int j = 0; j < NW; j++)
            bF[j] = (uint32_t)(ASTG + (wn + j*16 + khi*8 + rlo)*144 + 16*rmid);
    }

    float4 acc[2][2*NW];
    #pragma unroll
    for (int i = 0; i < 2; i++)
        #pragma unroll
        for (int j = 0; j < 2*NW; j++) acc[i][j] = make_float4(0.f,0.f,0.f,0.f);

    const int KT = K / 32;

    #pragma unroll
    for (int s = 0; s < 2; s++){
        uint32_t st = sbase + s*STG;
        #pragma unroll
        for (int r = 0; r < 4; r++) cp16(st + aSm[r], aG[r] + s*32);
        #pragma unroll
        for (int r = 0; r < NB4; r++) cp16(st + bSm[r], bG[r] + s*32);
        CP_COMMIT();
    }

    int cur = 0, nxtbuf = 2;
    for (int kt = 0; kt < KT; kt++){
        if (kt < KT-1) CP_WAIT1(); else CP_WAIT0();
        __syncthreads();
        if (kt + 2 < KT){
            uint32_t st = sbase + nxtbuf*STG;
            #pragma unroll
            for (int r = 0; r < 4; r++) cp16(st + aSm[r], aG[r] + (kt+2)*32);
            #pragma unroll
            for (int r = 0; r < NB4; r++) cp16(st + bSm[r], bG[r] + (kt+2)*32);
            CP_COMMIT();
        }
        uint32_t st = sbase + cur*STG;
        #pragma unroll
        for (int ks = 0; ks < 4; ks++){
            uint32_t a0[4], a1[4], bfr[NW][4];
            ldsm_x4(a0, st + aF[0] + ks*32);
            ldsm_x4(a1, st + aF[1] + ks*32);
            #pragma unroll
            for (int j = 0; j < NW; j++) ldsm_x4(bfr[j], st + bF[j] + ks*32);
            #pragma unroll
            for (int j = 0; j < NW; j++){
                mma_tf32(acc[0][2*j  ], a0, bfr[j][0], bfr[j][1]);
                mma_tf32(acc[0][2*j+1], a0, bfr[j][2], bfr[j][3]);
                mma_tf32(acc[1][2*j  ], a1, bfr[j][0], bfr[j][1]);
                mma_tf32(acc[1][2*j+1], a1, bfr[j][2], bfr[j][3]);
            }
        }
        cur = (cur + 1 == 3) ? 0 : cur + 1;
        nxtbuf = (nxtbuf + 1 == 3) ? 0 : nxtbuf + 1;
    }

    int tr = lane >> 2, tc = lane & 3;
    #pragma unroll
    for (int i = 0; i < 2; i++){
        int r0 = bm + wm + i*16 + tr;
        int r1 = r0 + 8;
        #pragma unroll
        for (int j = 0; j < 2*NW; j++){
            int col = bn + wn + j*8 + tc*2;
            float2 bb = *(const float2*)&bias[col];
            float4 v = acc[i][j];
            v.x += bb.x; v.y += bb.y; v.z += bb.x; v.w += bb.y;
            if (GELU){
                v.x = 0.5f*v.x*(1.0f + erff(v.x*0.7071067811865476f));
                v.y = 0.5f*v.y*(1.0f + erff(v.y*0.7071067811865476f));
                v.z = 0.5f*v.z*(1.0f + erff(v.z*0.7071067811865476f));
                v.w = 0.5f*v.w*(1.0f + erff(v.w*0.7071067811865476f));
            }
            if (RESID){
                float2 q0 = *(const float2*)&Res[(size_t)r0*N + col];
                float2 q1 = *(const float2*)&Res[(size_t)r1*N + col];
                v.x += q0.x; v.y += q0.y; v.z += q1.x; v.w += q1.y;
            }
            if (ROUND){
                v.x = to_tf32f(v.x); v.y = to_tf32f(v.y);
                v.z = to_tf32f(v.z); v.w = to_tf32f(v.w);
            }
            *(float2*)&C[(size_t)r0*N + col] = make_float2(v.x, v.y);
            *(float2*)&C[(size_t)r1*N + col] = make_float2(v.z, v.w);
        }
    }
}

// K6: LayerNorm over T, write final output
__global__ void k_ln(const float* __restrict__ lng, const float* __restrict__ lnb,
                     float* __restrict__ out){
    int row = blockIdx.x;
    const float* y = g_y + row*T_;
    int tid = threadIdx.x;
    float a = y[tid], b = y[tid + 256];
    __shared__ float red[8];
    int w = tid >> 5;
    float s = warp_sum(a + b);
    if ((tid & 31) == 0) red[w] = s;
    __syncthreads();
    float S = 0.f;
    #pragma unroll
    for (int k = 0; k < 8; k++) S += red[k];
    float mean = S * (1.f/512.f);
    float d0 = a - mean, d1 = b - mean;
    __syncthreads();
    float ss = warp_sum(d0*d0 + d1*d1);
    if ((tid & 31) == 0) red[w] = ss;
    __syncthreads();
    float SS = 0.f;
    #pragma unroll
    for (int k = 0; k < 8; k++) SS += red[k];
    float rs = rsqrtf(SS * (1.f/512.f) + 1e-5f);
    out[row*T_ + tid]       = d0*rs*lng[tid]       + lnb[tid];
    out[row*T_ + tid + 256] = d1*rs*lng[tid + 256] + lnb[tid + 256];
}

extern "C" void kernel_launch(void* const* d_in, const int* in_sizes, int n_in,
                              void* d_out, int out_size){
    const float* residual = (const float*)d_in[0];
    const float* bn_g = (const float*)d_in[1];
    const float* bn_b = (const float*)d_in[2];
    const float* ln_g = (const float*)d_in[3];
    const float* ln_b = (const float*)d_in[4];
    const float* W1   = (const float*)d_in[5];
    const float* b1   = (const float*)d_in[6];
    const float* W2   = (const float*)d_in[7];
    const float* b2   = (const float*)d_in[8];
    float* out = (float*)d_out;

    const int g1_smem = 3*(ASTG + 128*144);   // 110592 B
    const int g2_smem = 3*(ASTG + 64*144);    // 82944 B
    cudaFuncSetAttribute(k_attn, cudaFuncAttributeMaxDynamicSharedMemorySize, ATTN_SMEM);
    cudaFuncSetAttribute(k_mma<4, true,  true,  false>, cudaFuncAttributeMaxDynamicSharedMemorySize, g1_smem);
    cudaFuncSetAttribute(k_mma<2, false, false, true >, cudaFuncAttributeMaxDynamicSharedMemorySize, g2_smem);

    float *px2r, *ph, *py, *pw1t, *pw2t;
    cudaGetSymbolAddress((void**)&px2r, g_x2r);
    cudaGetSymbolAddress((void**)&ph,   g_h);
    cudaGetSymbolAddress((void**)&py,   g_y);
    cudaGetSymbolAddress((void**)&pw1t, g_w1t);
    cudaGetSymbolAddress((void**)&pw2t, g_w2t);

    // merged: weight transposes (blocks 0-1023) + corr softmax (blocks 1024-1039)
    k_pre<<<1024 + B_, 256>>>(W1, pw1t, W2, pw2t, residual);

    dim3 ga(T_/64, B_);
    k_attn<<<ga, 256, ATTN_SMEM>>>(residual);
    k_bn<<<D_, 512>>>(bn_g, bn_b);

    // GEMM1: h = tf32( GELU(x2r @ W1 + b1) )   [1536 x 1024 x 512], 128x128 tiles
    dim3 g1(H_/128, BD_/128);
    k_mma<4, true,  true,  false><<<g1, 256, g1_smem>>>(px2r, pw1t, b1, nullptr, ph, BD_, H_, T_);
    // GEMM2: y = h @ W2 + b2 + x2r             [1536 x 512 x 1024], 128x64 tiles
    dim3 g2(T_/64, BD_/128);
    k_mma<2, false, false, true ><<<g2, 256, g2_smem>>>(ph, pw2t, b2, px2r, py, BD_, T_, H_);

    k_ln<<<BD_, 256>>>(ln_g, ln_b, out);
}